// round 12
// baseline (speedup 1.0000x reference)
#include <cuda_runtime.h>
#include <cuda_bf16.h>
#include <math.h>

#define Nd    128
#define SLICE (Nd * Nd)          // 16384
#define VOL   (Nd * Nd * Nd)     // 2097152
#define NVOLS 8                  // 2 batches * 4 classes

__device__ double g_S1[NVOLS];
__device__ double g_S2[NVOLS];
__device__ double g_Num[NVOLS];
__device__ double g_Den[NVOLS];
__device__ __nv_bfloat16 g_scrA[(size_t)NVOLS * VOL];  // 32 MiB: W-blurred labels
__device__ __nv_bfloat16 g_scrB[(size_t)NVOLS * VOL];  // 32 MiB: WH-blurred labels

// Gaussian taps exp(-x^2/(2*25)), x=-4..4 (unnormalized, matches reference)
__constant__ float Gc[9] = {
    0.72614903f, 0.83527021f, 0.92311635f, 0.98019867f, 1.0f,
    0.98019867f, 0.92311635f, 0.83527021f, 0.72614903f
};

__device__ __forceinline__ void blockReduceAtomic(float a, float b, double* dA, double* dB) {
    const int tid  = threadIdx.x + threadIdx.y * blockDim.x;
    const int lane = tid & 31;
    const int wid  = tid >> 5;
    #pragma unroll
    for (int off = 16; off; off >>= 1) {
        a += __shfl_down_sync(0xffffffffu, a, off);
        b += __shfl_down_sync(0xffffffffu, b, off);
    }
    __shared__ float sa[16], sb[16];
    if (lane == 0) { sa[wid] = a; sb[wid] = b; }
    __syncthreads();
    if (tid == 0) {
        const int nw = (blockDim.x * blockDim.y) >> 5;
        double A = 0.0, B = 0.0;
        for (int i = 0; i < nw; ++i) { A += (double)sa[i]; B += (double)sb[i]; }
        atomicAdd(dA, A);
        atomicAdd(dB, B);
    }
}

__global__ void k_init() {
    const int i = threadIdx.x;
    if (i < NVOLS) { g_S1[i] = 0.0; g_S2[i] = 0.0; g_Num[i] = 0.0; g_Den[i] = 0.0; }
}

// ---------------------------------------------------------------------------
// Pass 1: W-blur labels -> g_scrA (bf16), fused with S1 = sum(p*in), S2 = sum(p).
// 16-row tile fully staged before a SINGLE sync (32 independent LDGs/thread).
// Thread-per-column smem reads are bank-conflict free.
// ---------------------------------------------------------------------------
__global__ void k_pass1(const float* __restrict__ labels, const float* __restrict__ inputs) {
    const int iv = blockIdx.x;
    const int rg = blockIdx.y;            // 16-row group, 0..1023
    const int w  = threadIdx.x;           // 0..127
    __shared__ float s[16][Nd + 8];
    const size_t rbase = (size_t)rg * 16 * Nd;
    const float* Lv = labels + (size_t)iv * VOL + rbase;
    const float* Iv = inputs + (size_t)(iv >> 2) * VOL + rbase;
    __nv_bfloat16* Ov = g_scrA + (size_t)iv * VOL + rbase;

    float pv[16], vv[16];
    #pragma unroll
    for (int r = 0; r < 16; ++r) pv[r] = Lv[r * Nd + w];
    #pragma unroll
    for (int r = 0; r < 16; ++r) vv[r] = Iv[r * Nd + w];

    float sumP = 0.f, sumPI = 0.f;
    #pragma unroll
    for (int r = 0; r < 16; ++r) {
        s[r][4 + w] = pv[r];
        sumP  += pv[r];
        sumPI += pv[r] * vv[r];
    }
    if (w < 4) {
        #pragma unroll
        for (int r = 0; r < 16; ++r) { s[r][w] = 0.f; s[r][Nd + 4 + w] = 0.f; }
    }
    __syncthreads();

    #pragma unroll
    for (int r = 0; r < 16; ++r) {
        float acc = 0.f;
        #pragma unroll
        for (int j = 0; j < 9; ++j) acc += Gc[j] * s[r][w + j];
        Ov[r * Nd + w] = __float2bfloat16(acc);
    }
    blockReduceAtomic(sumPI, sumP, &g_S1[iv], &g_S2[iv]);
}

// ---------------------------------------------------------------------------
// Pass 2: H-blur g_scrA -> g_scrB (bf16 ping-pong; no in-place race with the
// h-split). Rolling 9-tap window, x8 unroll with hoisted 8-load batches.
// Grid (Nd, NVOLS, 2): blockIdx.z selects h-half -> 2048 blocks for occupancy.
// ---------------------------------------------------------------------------
__global__ void k_pass2() {
    const int d  = blockIdx.x;            // 0..127
    const int iv = blockIdx.y;            // 0..7
    const int h0 = blockIdx.z * 64;       // 0 or 64
    const int w  = threadIdx.x;           // 0..127
    const __nv_bfloat16* __restrict__ src = g_scrA + (size_t)iv * VOL + (size_t)d * SLICE;
    __nv_bfloat16*       __restrict__ dst = g_scrB + (size_t)iv * VOL + (size_t)d * SLICE;

    float win[9];
    #pragma unroll
    for (int j = 0; j < 8; ++j) {
        const int hh = h0 - 4 + j;
        win[j] = (hh >= 0) ? __bfloat162float(src[hh * Nd + w]) : 0.f;
    }
    for (int hb = h0; hb < h0 + 64; hb += 8) {
        float nx[8];
        #pragma unroll
        for (int k = 0; k < 8; ++k) {         // 8 independent loads, batched
            const int hh = hb + k + 4;
            nx[k] = (hh < Nd) ? __bfloat162float(src[hh * Nd + w]) : 0.f;
        }
        #pragma unroll
        for (int k = 0; k < 8; ++k) {
            win[8] = nx[k];
            float acc = 0.f;
            #pragma unroll
            for (int j = 0; j < 9; ++j) acc += Gc[j] * win[j];
            dst[(hb + k) * Nd + w] = __float2bfloat16(acc);
            #pragma unroll
            for (int m = 0; m < 8; ++m) win[m] = win[m + 1];
        }
    }
}

// ---------------------------------------------------------------------------
// Pass 3: D-blur (rolling window over bf16 g_scrB) fused with weights and the
// num/den reductions via blur self-adjointness:
//   num = sum(blur(p) * p * w), den = sum(blur(p) * w), w = exp(-((in-mean)^2)^2)
// class_mean computed inline from g_S1/g_S2 (k_means kernel eliminated).
// x4 unroll, 12 batched independent loads per group.
// ---------------------------------------------------------------------------
__global__ void k_pass3(const float* __restrict__ labels, const float* __restrict__ inputs) {
    const int iv = blockIdx.x;                                  // 0..7
    const int h  = blockIdx.y * blockDim.y + threadIdx.y;       // 0..127
    const int d0 = blockIdx.z * 64;                             // 0 or 64
    const int w  = threadIdx.x;                                 // 0..127
    const float mean = (float)(g_S1[iv] / (g_S2[iv] + 1e-5 * (double)VOL));
    const __nv_bfloat16* __restrict__ S = g_scrB + (size_t)iv * VOL;
    const float* __restrict__ Lv = labels + (size_t)iv * VOL;
    const float* __restrict__ Iv = inputs + (size_t)(iv >> 2) * VOL;
    const int hw = h * Nd + w;

    float win[9];
    #pragma unroll
    for (int k = 0; k < 8; ++k) {
        const int d = d0 - 4 + k;
        win[k] = (d >= 0) ? __bfloat162float(S[(size_t)d * SLICE + hw]) : 0.f;
    }
    float numA = 0.f, denA = 0.f;
    for (int d = d0; d < d0 + 64; d += 4) {
        float nS[4], nP[4], nV[4];
        #pragma unroll
        for (int k = 0; k < 4; ++k) {         // 12 independent loads, batched
            const int dd = d + k;
            nS[k] = (dd + 4 < Nd) ? __bfloat162float(S[(size_t)(dd + 4) * SLICE + hw]) : 0.f;
            nP[k] = Lv[(size_t)dd * SLICE + hw];
            nV[k] = Iv[(size_t)dd * SLICE + hw];
        }
        #pragma unroll
        for (int k = 0; k < 4; ++k) {
            win[8] = nS[k];
            float bp = 0.f;
            #pragma unroll
            for (int j = 0; j < 9; ++j) bp += Gc[j] * win[j];
            float df = nV[k] - mean;
            df *= df;
            const float wgt = __expf(-df * df);
            numA += bp * nP[k] * wgt;
            denA += bp * wgt;
            #pragma unroll
            for (int m = 0; m < 8; ++m) win[m] = win[m + 1];
        }
    }
    blockReduceAtomic(numA, denA, &g_Num[iv], &g_Den[iv]);
}

__global__ void k_final(float* __restrict__ out) {
    if (threadIdx.x == 0) {
        double loss = 0.0;
        for (int k = 0; k < 4; ++k) {
            const double nn = g_Num[k] + g_Num[k + 4];
            const double dd = g_Den[k] + g_Den[k + 4];
            loss += fabs(nn / (dd + 1e-6));
        }
        out[0] = (float)(4.0 - loss);
    }
}

extern "C" void kernel_launch(void* const* d_in, const int* in_sizes, int n_in,
                              void* d_out, int out_size) {
    const float* labels = (const float*)d_in[0];
    const float* inputs = (const float*)d_in[1];
    if (n_in >= 2 && in_sizes[0] < in_sizes[1]) {
        labels = (const float*)d_in[1];
        inputs = (const float*)d_in[0];
    }
    k_init<<<1, 32>>>();
    k_pass1<<<dim3(NVOLS, 1024), 128>>>(labels, inputs);
    k_pass2<<<dim3(Nd, NVOLS, 2), 128>>>();
    k_pass3<<<dim3(NVOLS, 32, 2), dim3(128, 4)>>>(labels, inputs);
    k_final<<<1, 32>>>((float*)d_out);
    (void)out_size;
}

// round 15
// speedup vs baseline: 1.3811x; 1.3811x over previous
#include <cuda_runtime.h>
#include <cuda_bf16.h>
#include <math.h>

#define Nd    128
#define SLICE (Nd * Nd)          // 16384
#define VOL   (Nd * Nd * Nd)     // 2097152
#define NVOLS 8                  // 2 batches * 4 classes

__device__ double g_S1[NVOLS];
__device__ double g_S2[NVOLS];
__device__ double g_Num[NVOLS];
__device__ double g_Den[NVOLS];
__device__ __nv_bfloat16 g_scrB[(size_t)NVOLS * VOL];  // 32 MiB: WH-blurred labels

// Gaussian taps exp(-x^2/(2*25)), x=-4..4 (unnormalized, matches reference)
__constant__ float Gc[9] = {
    0.72614903f, 0.83527021f, 0.92311635f, 0.98019867f, 1.0f,
    0.98019867f, 0.92311635f, 0.83527021f, 0.72614903f
};

__device__ __forceinline__ void blockReduceAtomic(float a, float b, double* dA, double* dB) {
    const int tid  = threadIdx.x + threadIdx.y * blockDim.x;
    const int lane = tid & 31;
    const int wid  = tid >> 5;
    #pragma unroll
    for (int off = 16; off; off >>= 1) {
        a += __shfl_down_sync(0xffffffffu, a, off);
        b += __shfl_down_sync(0xffffffffu, b, off);
    }
    __shared__ float sa[16], sb_[16];
    if (lane == 0) { sa[wid] = a; sb_[wid] = b; }
    __syncthreads();   // doubles as the phase-A -> phase-B barrier in k_pass12
    if (tid == 0) {
        const int nw = (blockDim.x * blockDim.y) >> 5;
        double A = 0.0, B = 0.0;
        for (int i = 0; i < nw; ++i) { A += (double)sa[i]; B += (double)sb_[i]; }
        atomicAdd(dA, A);
        atomicAdd(dB, B);
    }
}

__global__ void k_init() {
    const int i = threadIdx.x;
    if (i < NVOLS) { g_S1[i] = 0.0; g_S2[i] = 0.0; g_Num[i] = 0.0; g_Den[i] = 0.0; }
}

// ---------------------------------------------------------------------------
// Fused pass 1+2 (per (iv,d) slice, 512 threads, 64KB dynamic smem):
//  Phase A: each warp owns 8 rows. float4 label+input loads (coalesced 512B),
//    S1/S2 sums, W-blur via +/-1-lane float4 shuffles (9-tap halo from 12
//    register values, no smem), store W-blurred row to smem (STS.128,
//    conflict-free).
//  [barrier = the __syncthreads inside blockReduceAtomic]
//  Phase B: thread -> (column w, 32-row group). H-blur via conflict-free
//    column reads using a straight-line carry8+load8 buffer (no shift MOVs),
//    write bf16 directly to g_scrB. g_scrA is eliminated entirely.
// ---------------------------------------------------------------------------
__global__ void __launch_bounds__(512) k_pass12(const float* __restrict__ labels,
                                                const float* __restrict__ inputs) {
    extern __shared__ float sb[];                 // [128][128] = 64 KB
    const int iv   = blockIdx.x;
    const int d    = blockIdx.y;
    const int t    = threadIdx.x;
    const int lane = t & 31;
    const int wp   = t >> 5;                      // warp 0..15
    const size_t vbase = (size_t)iv * VOL + (size_t)d * SLICE;
    const float4* __restrict__ L4 = (const float4*)(labels + vbase);
    const float4* __restrict__ I4 = (const float4*)(inputs + (size_t)(iv >> 2) * VOL
                                                           + (size_t)d * SLICE);

    // ---- Phase A: W-blur 8 rows per warp ----
    float sumP = 0.f, sumPI = 0.f;
    #pragma unroll
    for (int r = 0; r < 8; ++r) {
        const int h   = wp * 8 + r;
        const int idx = h * 32 + lane;
        const float4 p  = L4[idx];
        const float4 vi = I4[idx];
        sumP  += (p.x + p.y) + (p.z + p.w);
        sumPI += (p.x * vi.x + p.y * vi.y) + (p.z * vi.z + p.w * vi.w);

        float a[12];
        a[0] = __shfl_up_sync(0xffffffffu, p.x, 1);
        a[1] = __shfl_up_sync(0xffffffffu, p.y, 1);
        a[2] = __shfl_up_sync(0xffffffffu, p.z, 1);
        a[3] = __shfl_up_sync(0xffffffffu, p.w, 1);
        a[4] = p.x; a[5] = p.y; a[6] = p.z; a[7] = p.w;
        a[8]  = __shfl_down_sync(0xffffffffu, p.x, 1);
        a[9]  = __shfl_down_sync(0xffffffffu, p.y, 1);
        a[10] = __shfl_down_sync(0xffffffffu, p.z, 1);
        a[11] = __shfl_down_sync(0xffffffffu, p.w, 1);
        if (lane == 0)  { a[0] = a[1] = a[2]  = a[3]  = 0.f; }
        if (lane == 31) { a[8] = a[9] = a[10] = a[11] = 0.f; }

        float4 o;
        {
            float o0 = 0.f, o1 = 0.f, o2 = 0.f, o3 = 0.f;
            #pragma unroll
            for (int j = 0; j < 9; ++j) {
                o0 += Gc[j] * a[j];
                o1 += Gc[j] * a[j + 1];
                o2 += Gc[j] * a[j + 2];
                o3 += Gc[j] * a[j + 3];
            }
            o = make_float4(o0, o1, o2, o3);
        }
        ((float4*)(sb + h * Nd))[lane] = o;       // STS.128, conflict-free
    }

    // barrier inside (orders phase-A smem stores before phase-B reads)
    blockReduceAtomic(sumPI, sumP, &g_S1[iv], &g_S2[iv]);

    // ---- Phase B: H-blur, 32 rows per thread, straight-line buffer ----
    const int w2 = t & 127;                       // column
    const int hg = t >> 7;                        // row group 0..3
    __nv_bfloat16* __restrict__ dst = g_scrB + vbase;

    float carry[8];
    #pragma unroll
    for (int k = 0; k < 8; ++k) {
        const int hh = hg * 32 - 4 + k;
        carry[k] = (hh >= 0) ? sb[hh * Nd + w2] : 0.f;
    }
    #pragma unroll
    for (int g = 0; g < 4; ++g) {
        const int hb = hg * 32 + g * 8;
        float nx[8];
        #pragma unroll
        for (int k = 0; k < 8; ++k) {             // 8 independent LDS, batched
            const int hh = hb + 4 + k;
            nx[k] = (hh < Nd) ? sb[hh * Nd + w2] : 0.f;
        }
        float buf[16];
        #pragma unroll
        for (int k = 0; k < 8; ++k) { buf[k] = carry[k]; buf[8 + k] = nx[k]; }
        #pragma unroll
        for (int k = 0; k < 8; ++k) {
            float acc = 0.f;
            #pragma unroll
            for (int j = 0; j < 9; ++j) acc += Gc[j] * buf[k + j];
            dst[(hb + k) * Nd + w2] = __float2bfloat16(acc);
        }
        #pragma unroll
        for (int k = 0; k < 8; ++k) carry[k] = nx[k];
    }
}

// ---------------------------------------------------------------------------
// Pass 3: D-blur over bf16 g_scrB fused with weights + num/den reductions
// (blur self-adjointness). Straight-line carry8+load8 buffer: no window-shift
// MOVs, 24 independent loads batched per 8-output group (MLP ~24).
//   num = sum(blur3(p) * p * w), den = sum(blur3(p) * w),
//   w = exp(-((in-mean)^2)^2), mean computed inline from g_S1/g_S2.
// ---------------------------------------------------------------------------
__global__ void __launch_bounds__(256) k_pass3(const float* __restrict__ labels,
                                               const float* __restrict__ inputs) {
    const int iv = blockIdx.x;                                  // 0..7
    const int h  = blockIdx.y * blockDim.y + threadIdx.y;       // 0..127
    const int d0 = blockIdx.z * 64;                             // 0 or 64
    const int w  = threadIdx.x;                                 // 0..127
    const float mean = (float)(g_S1[iv] / (g_S2[iv] + 1e-5 * (double)VOL));
    const __nv_bfloat16* __restrict__ S = g_scrB + (size_t)iv * VOL;
    const float* __restrict__ Lv = labels + (size_t)iv * VOL;
    const float* __restrict__ Iv = inputs + (size_t)(iv >> 2) * VOL;
    const int hw = h * Nd + w;

    float carry[8];
    #pragma unroll
    for (int k = 0; k < 8; ++k) {
        const int dd = d0 - 4 + k;
        carry[k] = (dd >= 0) ? __bfloat162float(S[(size_t)dd * SLICE + hw]) : 0.f;
    }
    float numA = 0.f, denA = 0.f;
    for (int d = d0; d < d0 + 64; d += 8) {
        float nS[8], nP[8], nV[8];
        #pragma unroll
        for (int k = 0; k < 8; ++k) {             // 24 independent loads, batched
            const int dd = d + k;
            nS[k] = (dd + 4 < Nd) ? __bfloat162float(S[(size_t)(dd + 4) * SLICE + hw]) : 0.f;
            nP[k] = Lv[(size_t)dd * SLICE + hw];
            nV[k] = Iv[(size_t)dd * SLICE + hw];
        }
        float buf[16];
        #pragma unroll
        for (int k = 0; k < 8; ++k) { buf[k] = carry[k]; buf[8 + k] = nS[k]; }
        #pragma unroll
        for (int k = 0; k < 8; ++k) {
            float bp = 0.f;
            #pragma unroll
            for (int j = 0; j < 9; ++j) bp += Gc[j] * buf[k + j];
            float df = nV[k] - mean;
            df *= df;
            const float wgt = __expf(-df * df);
            numA += bp * nP[k] * wgt;
            denA += bp * wgt;
        }
        #pragma unroll
        for (int k = 0; k < 8; ++k) carry[k] = nS[k];
    }
    blockReduceAtomic(numA, denA, &g_Num[iv], &g_Den[iv]);
}

__global__ void k_final(float* __restrict__ out) {
    if (threadIdx.x == 0) {
        double loss = 0.0;
        for (int k = 0; k < 4; ++k) {
            const double nn = g_Num[k] + g_Num[k + 4];
            const double dd = g_Den[k] + g_Den[k + 4];
            loss += fabs(nn / (dd + 1e-6));
        }
        out[0] = (float)(4.0 - loss);
    }
}

extern "C" void kernel_launch(void* const* d_in, const int* in_sizes, int n_in,
                              void* d_out, int out_size) {
    const float* labels = (const float*)d_in[0];
    const float* inputs = (const float*)d_in[1];
    if (n_in >= 2 && in_sizes[0] < in_sizes[1]) {
        labels = (const float*)d_in[1];
        inputs = (const float*)d_in[0];
    }
    cudaFuncSetAttribute(k_pass12, cudaFuncAttributeMaxDynamicSharedMemorySize, 65536);
    k_init<<<1, 32>>>();
    k_pass12<<<dim3(NVOLS, Nd), 512, 65536>>>(labels, inputs);
    k_pass3<<<dim3(NVOLS, 64, 2), dim3(128, 2)>>>(labels, inputs);
    k_final<<<1, 32>>>((float*)d_out);
    (void)out_size;
}